// round 15
// baseline (speedup 1.0000x reference)
#include <cuda_runtime.h>
#include <math.h>
#include <stdint.h>

#define Bc 16
#define Sc 2048
#define Hc 1024
#define Nc 128
#define ROWS (Bc*Nc)          // 2048
#define KSEGS 4
#define KTOT (KSEGS*Hc)       // 4096
#define MT 128                // M tile
#define NTt 128               // N tile
#define KC 32                 // K chunk (fp32)
#define NCH (KTOT/KC)         // 128
#define MTILES 17
#define NTILES (Hc/NTt)       // 8

#define KCp 36                // padded smem row stride (floats)
#define TILE_F (128*KCp)      // 4608 floats per A or B tile
#define STAGE_F (2*TILE_F)    // 9216 floats = 36864 B per stage
#define NSTG 3
#define SMEM_BYTES (NSTG*STAGE_F*4)   // 110592

#define DW_BLOCKS 4096        // 1M float4 / 256

// ---------------- scratch (device globals) ---------------------------------
__device__ float g_A[(size_t)ROWS*KTOT];     // [Init|u|S0|S1] rows, tf32-rounded
__device__ float g_alpha[ROWS];
__device__ float g_sc[ROWS];                 // mask/denom per row
__device__ float g_wfT[(size_t)Hc*Hc];       // w_f transposed, K-major
__device__ float g_dW[(size_t)4*Hc*Hc];      // W_{4+m} - W_m, m=0..3
__device__ float g_Acc[Bc*2*Hc];             // per-batch channel sums A_c
__device__ float g_y[Bc*2*Hc];               // rank-1 correction y[b][a][n]
__device__ int   g_perm[MTILES*MT];
__device__ int   g_meta[4];

// ---------------- helpers ---------------------------------------------------
__device__ __forceinline__ float to_tf32(float x){
    float r; asm("cvt.rna.tf32.f32 %0, %1;" : "=f"(r) : "f"(x)); return r;
}
__device__ __forceinline__ void mma8(float* c, const uint32_t* a, const uint32_t* b){
    asm volatile("mma.sync.aligned.m16n8k8.row.col.f32.tf32.tf32.f32 "
        "{%0,%1,%2,%3}, {%4,%5,%6,%7}, {%8,%9}, {%0,%1,%2,%3};"
        : "+f"(c[0]), "+f"(c[1]), "+f"(c[2]), "+f"(c[3])
        : "r"(a[0]), "r"(a[1]), "r"(a[2]), "r"(a[3]), "r"(b[0]), "r"(b[1]));
}
__device__ __forceinline__ void cpa16(uint32_t dst, const void* src, int sz){
    asm volatile("cp.async.ca.shared.global [%0], [%1], 16, %2;"
                 :: "r"(dst), "l"(src), "r"(sz) : "memory");
}

// ---------------- kernel 1: gather Init rows + alpha -----------------------
__global__ void k_gather(const float* __restrict__ we, const int* __restrict__ ids,
                         const float* __restrict__ w_alpha, const float* __restrict__ b_alpha) {
    int row = blockIdx.x;
    int b = row >> 7;
    int id = ids[row];
    int idc = min(max(id, 0), Sc - 1);
    const float* src = we + ((size_t)b*Sc + idc)*Hc;
    float partial = 0.f;
    #pragma unroll 4
    for (int h = threadIdx.x; h < Hc; h += 256) {
        float v = src[h];
        g_A[(size_t)row*KTOT + h] = to_tf32(v);
        partial += v * w_alpha[h];
    }
    __shared__ float red[256];
    red[threadIdx.x] = partial;
    __syncthreads();
    for (int s = 128; s > 0; s >>= 1) {
        if (threadIdx.x < s) red[threadIdx.x] += red[threadIdx.x + s];
        __syncthreads();
    }
    if (threadIdx.x == 0) {
        float x = red[0] + b_alpha[0];
        g_alpha[row] = 1.f / (1.f + expf(-x));
    }
}

// ---------------- kernel 1b: transpose w_f -> K-major (tf32) ---------------
__global__ void k_transpose(const float* __restrict__ w) {
    __shared__ float t[32][33];
    int bx = blockIdx.x*32, by = blockIdx.y*32;
    for (int r = threadIdx.y; r < 32; r += 8)
        t[r][threadIdx.x] = w[(size_t)(by + r)*Hc + bx + threadIdx.x];
    __syncthreads();
    for (int r = threadIdx.y; r < 32; r += 8)
        g_wfT[(size_t)(bx + r)*Hc + by + threadIdx.x] = to_tf32(t[threadIdx.x][r]);
}

// ---------------- kernel 1c: dW = W_{4+m}-W_m  + fused row permutation -----
__global__ void k_dwperm(const float* __restrict__ W_r, const int* __restrict__ is_resp) {
    if (blockIdx.x < DW_BLOCKS) {
        size_t i = (size_t)blockIdx.x*256 + threadIdx.x;     // float4 index
        const float4* w4 = (const float4*)W_r;
        float4 lo = w4[i];
        float4 hi = w4[i + (size_t)Hc*Hc];                   // +4 matrices
        ((float4*)g_dW)[i] = make_float4(hi.x-lo.x, hi.y-lo.y, hi.z-lo.z, hi.w-lo.w);
        return;
    }
    // --- perm block (warp-aggregated atomics) ---
    __shared__ int red[256];
    __shared__ int cnt[2];
    int tid = threadIdx.x;
    int lane = tid & 31;
    unsigned lt = (1u << lane) - 1u;
    int local0 = 0;
    for (int r = tid; r < ROWS; r += 256)
        local0 += (is_resp[r] == 1) ? 0 : 1;
    red[tid] = local0;
    __syncthreads();
    for (int s = 128; s > 0; s >>= 1) {
        if (tid < s) red[tid] += red[tid + s];
        __syncthreads();
    }
    int n0 = red[0];
    int g0t = (n0 + MT - 1) / MT;
    if (tid == 0) { cnt[0] = 0; cnt[1] = g0t * MT; g_meta[0] = g0t; }
    for (int s = tid; s < MTILES*MT; s += 256) g_perm[s] = -1;
    __syncthreads();
    for (int r = tid; r < ROWS; r += 256) {
        int grp = (is_resp[r] == 1) ? 1 : 0;
        unsigned m1 = __ballot_sync(0xffffffffu, grp);
        unsigned m0 = ~m1;
        int l0 = __ffs(m0) - 1, l1 = __ffs(m1) - 1;
        int base0 = 0, base1 = 0;
        if (m0 && lane == l0) base0 = atomicAdd(&cnt[0], __popc(m0));
        if (m1 && lane == l1) base1 = atomicAdd(&cnt[1], __popc(m1));
        if (m0) base0 = __shfl_sync(0xffffffffu, base0, l0);
        if (m1) base1 = __shfl_sync(0xffffffffu, base1, l1);
        int pos = grp ? (base1 + __popc(m1 & lt)) : (base0 + __popc(m0 & lt));
        g_perm[pos] = r;
    }
}

// ---------------- kernel 2: sorted-prefix aggregation ----------------------
// writes segs: u = -sc*alpha*Init, S0*sc, S1*sc; plus g_Acc, g_sc.
__global__ void k_agg(const float* __restrict__ numbers, const int* __restrict__ is_resp,
                      const int* __restrict__ ids) {
    int b = blockIdx.x;
    int tid = threadIdx.x;
    int h4 = blockIdx.y * 128 + tid;            // float4 column 0..255
    __shared__ float s_num[Nc], s_w[Nc], s_scale[Nc];
    __shared__ int s_order[Nc], s_c[Nc];
    __shared__ unsigned char s_newgrp[Nc];
    __shared__ int s_cnt;
    if (tid == 0) s_cnt = 0;
    __syncthreads();
    {
        int i = tid;                             // 128 threads == Nc
        s_num[i] = numbers[b*Nc + i];
        s_c[i] = (is_resp[b*Nc + i] == 1) ? 1 : 0;
        int valid = (ids[b*Nc + i] >= 0) ? 1 : 0;
        s_w[i] = valid ? g_alpha[b*Nc + i] : 0.f;
        s_scale[i] = (float)valid;
        if (valid) atomicAdd(&s_cnt, 1);
    }
    __syncthreads();
    float denom = fmaxf((float)(s_cnt - 1), 1.f);
    {
        int i = tid;
        float ni = s_num[i];
        int pos = 0;
        for (int j = 0; j < Nc; j++) {
            float nj = s_num[j];
            pos += (int)((nj < ni) || (nj == ni && j < i));
        }
        s_order[pos] = i;
        s_scale[i] = s_scale[i] / denom;
    }
    __syncthreads();
    {
        int t = tid;
        s_newgrp[t] = (t == 0) || (s_num[s_order[t]] != s_num[s_order[t-1]]);
    }
    __syncthreads();
    if (blockIdx.y == 0) g_sc[b*Nc + tid] = s_scale[tid];

    const float4* initb = (const float4*)g_A + (size_t)(b*Nc)*(KTOT/4) + h4;
    float4 A0 = make_float4(0,0,0,0), A1 = A0;
    #pragma unroll 2
    for (int j = 0; j < Nc; j++) {
        float4 v = initb[(size_t)j*(KTOT/4)];
        float w = s_w[j];
        if (s_c[j]) { A1.x += w*v.x; A1.y += w*v.y; A1.z += w*v.z; A1.w += w*v.w; }
        else        { A0.x += w*v.x; A0.y += w*v.y; A0.z += w*v.z; A0.w += w*v.w; }
    }
    ((float4*)g_Acc)[(size_t)(b*2 + 0)*(Hc/4) + h4] = A0;
    ((float4*)g_Acc)[(size_t)(b*2 + 1)*(Hc/4) + h4] = A1;

    float4 p0 = make_float4(0,0,0,0), p1 = p0, r0 = p0, r1 = p0;
    float4 v = initb[(size_t)s_order[0]*(KTOT/4)];
    for (int t = 0; t < Nc; t++) {
        int j = s_order[t];
        float4 vn;
        if (t + 1 < Nc) vn = initb[(size_t)s_order[t+1]*(KTOT/4)];
        if (s_newgrp[t]) { p0 = r0; p1 = r1; }
        float w = s_w[j], sc = s_scale[j];
        int c = s_c[j];
        float mu = -sc * w;
        float4* xb = (float4*)g_A + (size_t)(b*Nc + j)*(KTOT/4) + (Hc/4) + h4;
        xb[0]        = make_float4(to_tf32(mu*v.x), to_tf32(mu*v.y), to_tf32(mu*v.z), to_tf32(mu*v.w));
        xb[Hc/4]     = make_float4(to_tf32(p0.x*sc), to_tf32(p0.y*sc), to_tf32(p0.z*sc), to_tf32(p0.w*sc));
        xb[2*(Hc/4)] = make_float4(to_tf32(p1.x*sc), to_tf32(p1.y*sc), to_tf32(p1.z*sc), to_tf32(p1.w*sc));
        float4 wv = make_float4(w*v.x, w*v.y, w*v.z, w*v.w);
        if (c) { r1.x += wv.x; r1.y += wv.y; r1.z += wv.z; r1.w += wv.w; }
        else   { r0.x += wv.x; r0.y += wv.y; r0.z += wv.z; r0.w += wv.w; }
        v = vn;
    }
}

// ---------------- kernel 2b: rank-1 correction  y[b][a] = Σ_c A_c @ W_{2a+c}ᵀ
__global__ void k_y(const float* __restrict__ W_r) {
    int a = blockIdx.y;
    int warp = threadIdx.x >> 5, lane = threadIdx.x & 31;
    const float* W0 = W_r + (size_t)(2*a)*Hc*Hc;
    const float* W1 = W_r + (size_t)(2*a + 1)*Hc*Hc;
    for (int q = 0; q < 8; q++) {
        int n = blockIdx.x*64 + warp*8 + q;
        const float* w0 = W0 + (size_t)n*Hc;
        const float* w1 = W1 + (size_t)n*Hc;
        float accb[Bc];
        #pragma unroll
        for (int b = 0; b < Bc; b++) accb[b] = 0.f;
        for (int h = lane; h < Hc; h += 32) {
            float w0v = w0[h], w1v = w1[h];
            #pragma unroll
            for (int b = 0; b < Bc; b++) {
                accb[b] += g_Acc[(size_t)(b*2 + 0)*Hc + h] * w0v
                         + g_Acc[(size_t)(b*2 + 1)*Hc + h] * w1v;
            }
        }
        #pragma unroll
        for (int b = 0; b < Bc; b++) {
            float vsum = accb[b];
            #pragma unroll
            for (int off = 16; off > 0; off >>= 1)
                vsum += __shfl_down_sync(0xffffffffu, vsum, off);
            if (lane == 0) g_y[(size_t)(b*2 + a)*Hc + n] = vsum;
        }
    }
}

// ---------------- kernel 4: tf32 mma.sync GEMM, cp.async 3-stage -----------
// 512 threads, 16 warps (4x4), warp tile 32x32. smem [row][36] padded layout.
__global__ void __launch_bounds__(512, 1)
k_mma(const float* __restrict__ b_f, const float* __restrict__ W_r,
      float* __restrict__ out) {
    extern __shared__ float sdyn[];
    __shared__ int s_rows[MT];
    __shared__ const float* s_Bp[KSEGS];
    __shared__ int s_a;

    int tid = threadIdx.x;
    int wid = tid >> 5;
    int lane = tid & 31;
    int g = lane >> 2, tig = lane & 3;
    int wr = wid >> 2;                // 0..3 (32-row strip)
    int wc = wid & 3;                 // 0..3 (32-col strip)
    int mt = blockIdx.y, nt = blockIdx.x;
    int ncol = nt * NTt;

    if (tid < MT) s_rows[tid] = g_perm[mt*MT + tid];
    if (tid == 0) {
        int a = (mt >= g_meta[0]) ? 1 : 0;
        s_a = a;
        s_Bp[0] = g_wfT;
        s_Bp[1] = W_r + (size_t)(3*a)*Hc*Hc;       // self term weight W_{3a}
        s_Bp[2] = g_dW + (size_t)(2*a    )*Hc*Hc;  // ΔW_{a,0}
        s_Bp[3] = g_dW + (size_t)(2*a + 1)*Hc*Hc;  // ΔW_{a,1}
    }
    __syncthreads();

    // copy map: thread t owns 16B units t and t+512 of each 1024-unit tile.
    int mu0 = tid >> 3;               // row 0..63
    int seg = tid & 7;                // 16B segment within 128B row payload
    int mu1 = mu0 + 64;
    int rA0 = s_rows[mu0], rA1 = s_rows[mu1];
    const float* srcA0 = (rA0 >= 0) ? (g_A + (size_t)rA0*KTOT + seg*4) : g_A;
    const float* srcA1 = (rA1 >= 0) ? (g_A + (size_t)rA1*KTOT + seg*4) : g_A;
    int szA0 = (rA0 >= 0) ? 16 : 0;
    int szA1 = (rA1 >= 0) ? 16 : 0;
    int d0 = mu0*KCp*4 + seg*16;      // byte offset within a tile
    int d1 = mu1*KCp*4 + seg*16;
    size_t bc0 = (size_t)(ncol + mu0)*Hc + seg*4;
    size_t bc1 = (size_t)(ncol + mu1)*Hc + seg*4;
    uint32_t sb = (uint32_t)__cvta_generic_to_shared(sdyn);

    auto issue = [&](int kc) {
        int st = kc % NSTG;
        uint32_t ab = sb + st*(STAGE_F*4);
        uint32_t bb = ab + TILE_F*4;
        int koff = kc * KC;
        cpa16(ab + d0, srcA0 + koff, szA0);
        cpa16(ab + d1, srcA1 + koff, szA1);
        const float* Bs = s_Bp[kc >> 5];
        int kin = (kc & 31) * KC;
        cpa16(bb + d0, Bs + bc0 + kin, 16);
        cpa16(bb + d1, Bs + bc1 + kin, 16);
        asm volatile("cp.async.commit_group;" ::: "memory");
    };

    issue(0);
    issue(1);

    float acc[2][4][4];
    #pragma unroll
    for (int i = 0; i < 2; i++)
        #pragma unroll
        for (int j = 0; j < 4; j++)
            #pragma unroll
            for (int q = 0; q < 4; q++) acc[i][j][q] = 0.f;

    for (int kc = 0; kc < NCH; kc++) {
        if (kc + 1 < NCH) asm volatile("cp.async.wait_group 1;" ::: "memory");
        else              asm volatile("cp.async.wait_group 0;" ::: "memory");
        __syncthreads();
        if (kc + 2 < NCH) issue(kc + 2);

        const float* As = sdyn + (kc % NSTG)*STAGE_F;
        const float* Bs = As + TILE_F;
        #pragma unroll
        for (int ks = 0; ks < 4; ks++) {
            int k0 = 8*ks + tig;
            uint32_t afr[2][4], bfr[4][2];
            #pragma unroll
            for (int rm = 0; rm < 2; rm++) {
                int m = 32*wr + 16*rm + g;
                afr[rm][0] = __float_as_uint(As[m*KCp + k0]);
                afr[rm][1] = __float_as_uint(As[(m+8)*KCp + k0]);
                afr[rm][2] = __float_as_uint(As[m*KCp + k0 + 4]);
                afr[rm][3] = __float_as_uint(As[(m+8)*KCp + k0 + 4]);
            }
            #pragma unroll
            for (int nb = 0; nb < 4; nb++) {
                int n = 32*wc + 8*nb + g;
                bfr[nb][0] = __float_as_uint(Bs[n*KCp + k0]);
                bfr[nb][1] = __float_as_uint(Bs[n*KCp + k0 + 4]);
            }
            #pragma unroll
            for (int rm = 0; rm < 2; rm++)
                #pragma unroll
                for (int nb = 0; nb < 4; nb++)
                    mma8(acc[rm][nb], afr[rm], bfr[nb]);
        }
    }

    // ---- epilogue: bias + rank-1 correction + relu + scatter ------------
    int aa = s_a;
    #pragma unroll
    for (int rm = 0; rm < 2; rm++) {
        int m0 = 32*wr + 16*rm + g;
        int row0 = s_rows[m0], row1 = s_rows[m0 + 8];
        #pragma unroll
        for (int nb = 0; nb < 4; nb++) {
            int col = ncol + 32*wc + 8*nb + 2*tig;
            float b0v = b_f[col], b1v = b_f[col + 1];
            if (row0 >= 0) {
                int b = row0 >> 7;
                float2 yv = *(const float2*)(g_y + (size_t)(b*2 + aa)*Hc + col);
                float scv = g_sc[row0];
                float v0 = acc[rm][nb][0] + b0v + scv*yv.x; v0 = v0 > 0.f ? v0 : 0.f;
                float v1 = acc[rm][nb][1] + b1v + scv*yv.y; v1 = v1 > 0.f ? v1 : 0.f;
                *(float2*)(out + (size_t)row0*Hc + col) = make_float2(v0, v1);
            }
            if (row1 >= 0) {
                int b = row1 >> 7;
                float2 yv = *(const float2*)(g_y + (size_t)(b*2 + aa)*Hc + col);
                float scv = g_sc[row1];
                float v2 = acc[rm][nb][2] + b0v + scv*yv.x; v2 = v2 > 0.f ? v2 : 0.f;
                float v3 = acc[rm][nb][3] + b1v + scv*yv.y; v3 = v3 > 0.f ? v3 : 0.f;
                *(float2*)(out + (size_t)row1*Hc + col) = make_float2(v2, v3);
            }
        }
    }
}

// ---------------------------------------------------------------------------
extern "C" void kernel_launch(void* const* d_in, const int* in_sizes, int n_in,
                              void* d_out, int out_size) {
    const float* word_emb = (const float*)d_in[0];
    const int*   num_ids  = (const int*)  d_in[1];
    const int*   is_resp  = (const int*)  d_in[2];
    const float* numbers  = (const float*)d_in[3];
    const float* w_alpha  = (const float*)d_in[4];
    const float* b_alpha  = (const float*)d_in[5];
    const float* w_f      = (const float*)d_in[6];
    const float* b_f      = (const float*)d_in[7];
    const float* W_r      = (const float*)d_in[8];
    float* out = (float*)d_out;

    k_gather<<<ROWS, 256>>>(word_emb, num_ids, w_alpha, b_alpha);         // 0
    k_transpose<<<dim3(Hc/32, Hc/32), dim3(32, 8)>>>(w_f);                // 1
    k_dwperm<<<DW_BLOCKS + 1, 256>>>(W_r, is_resp);                       // 2
    k_agg<<<dim3(Bc, 2), 128>>>(numbers, is_resp, num_ids);               // 3
    k_y<<<dim3(16, 2), 256>>>(W_r);                                       // 4
    cudaFuncSetAttribute(k_mma, cudaFuncAttributeMaxDynamicSharedMemorySize, SMEM_BYTES);
    k_mma<<<dim3(NTILES, MTILES), 512, SMEM_BYTES>>>(b_f, W_r, out);      // 5 (ncu -s 5 target)
}

// round 16
// speedup vs baseline: 1.8674x; 1.8674x over previous
#include <cuda_runtime.h>
#include <math.h>
#include <stdint.h>

#define Bc 16
#define Sc 2048
#define Hc 1024
#define Nc 128
#define ROWS (Bc*Nc)          // 2048
#define KSEGS 5
#define KTOT (KSEGS*Hc)       // 5120
#define MT 128                // M tile
#define NTt 128               // N tile
#define KC 32                 // K chunk (fp32)
#define NCH (KTOT/KC)         // 160
#define MTILES 17
#define NTILES (Hc/NTt)       // 8

#define KCp 36                // padded smem row stride (floats)
#define TILE_F (128*KCp)      // 4608 floats per A or B tile
#define STAGE_F (2*TILE_F)    // 9216 floats = 36864 B per stage
#define NSTG 3
#define SMEM_BYTES (NSTG*STAGE_F*4)   // 110592

// ---------------- scratch (device globals) ---------------------------------
__device__ float g_A[(size_t)ROWS*KTOT];     // [Init|x0..x3] rows, tf32-rounded
__device__ float g_alpha[ROWS];
__device__ float g_wfT[(size_t)Hc*Hc];       // w_f transposed, K-major
__device__ int   g_perm[MTILES*MT];
__device__ int   g_meta[4];

// ---------------- helpers ---------------------------------------------------
__device__ __forceinline__ float to_tf32(float x){
    float r; asm("cvt.rna.tf32.f32 %0, %1;" : "=f"(r) : "f"(x)); return r;
}
__device__ __forceinline__ void mma8(float* c, const uint32_t* a, const uint32_t* b){
    asm volatile("mma.sync.aligned.m16n8k8.row.col.f32.tf32.tf32.f32 "
        "{%0,%1,%2,%3}, {%4,%5,%6,%7}, {%8,%9}, {%0,%1,%2,%3};"
        : "+f"(c[0]), "+f"(c[1]), "+f"(c[2]), "+f"(c[3])
        : "r"(a[0]), "r"(a[1]), "r"(a[2]), "r"(a[3]), "r"(b[0]), "r"(b[1]));
}
__device__ __forceinline__ void cpa16(uint32_t dst, const void* src, int sz){
    asm volatile("cp.async.ca.shared.global [%0], [%1], 16, %2;"
                 :: "r"(dst), "l"(src), "r"(sz) : "memory");
}

// ---------------- kernel 1: gather Init rows + alpha -----------------------
__global__ void k_gather(const float* __restrict__ we, const int* __restrict__ ids,
                         const float* __restrict__ w_alpha, const float* __restrict__ b_alpha) {
    int row = blockIdx.x;
    int b = row >> 7;
    int id = ids[row];
    int idc = min(max(id, 0), Sc - 1);
    const float* src = we + ((size_t)b*Sc + idc)*Hc;
    float partial = 0.f;
    #pragma unroll 4
    for (int h = threadIdx.x; h < Hc; h += 256) {
        float v = src[h];
        g_A[(size_t)row*KTOT + h] = to_tf32(v);
        partial += v * w_alpha[h];
    }
    __shared__ float red[256];
    red[threadIdx.x] = partial;
    __syncthreads();
    for (int s = 128; s > 0; s >>= 1) {
        if (threadIdx.x < s) red[threadIdx.x] += red[threadIdx.x + s];
        __syncthreads();
    }
    if (threadIdx.x == 0) {
        float x = red[0] + b_alpha[0];
        g_alpha[row] = 1.f / (1.f + expf(-x));
    }
}

// ---------------- kernel 1b: transpose w_f (tf32) + fused row permutation --
__global__ void k_transperm(const float* __restrict__ w, const int* __restrict__ is_resp) {
    if (blockIdx.x < 32) {
        // transpose tile
        __shared__ float t[32][33];
        int bx = blockIdx.x*32, by = blockIdx.y*32;
        for (int r = threadIdx.y; r < 32; r += 8)
            t[r][threadIdx.x] = w[(size_t)(by + r)*Hc + bx + threadIdx.x];
        __syncthreads();
        for (int r = threadIdx.y; r < 32; r += 8)
            g_wfT[(size_t)(bx + r)*Hc + by + threadIdx.x] = to_tf32(t[threadIdx.x][r]);
        return;
    }
    if (blockIdx.y != 0) return;
    // --- perm block (warp-aggregated atomics), 256 threads -----------------
    __shared__ int red[256];
    __shared__ int cnt[2];
    int tid = threadIdx.y*32 + threadIdx.x;
    int lane = tid & 31;
    unsigned lt = (1u << lane) - 1u;
    int local0 = 0;
    for (int r = tid; r < ROWS; r += 256)
        local0 += (is_resp[r] == 1) ? 0 : 1;
    red[tid] = local0;
    __syncthreads();
    for (int s = 128; s > 0; s >>= 1) {
        if (tid < s) red[tid] += red[tid + s];
        __syncthreads();
    }
    int n0 = red[0];
    int g0t = (n0 + MT - 1) / MT;
    if (tid == 0) { cnt[0] = 0; cnt[1] = g0t * MT; g_meta[0] = g0t; }
    for (int s = tid; s < MTILES*MT; s += 256) g_perm[s] = -1;
    __syncthreads();
    for (int r = tid; r < ROWS; r += 256) {
        int grp = (is_resp[r] == 1) ? 1 : 0;
        unsigned m1 = __ballot_sync(0xffffffffu, grp);
        unsigned m0 = ~m1;
        int l0 = __ffs(m0) - 1, l1 = __ffs(m1) - 1;
        int base0 = 0, base1 = 0;
        if (m0 && lane == l0) base0 = atomicAdd(&cnt[0], __popc(m0));
        if (m1 && lane == l1) base1 = atomicAdd(&cnt[1], __popc(m1));
        if (m0) base0 = __shfl_sync(0xffffffffu, base0, l0);
        if (m1) base1 = __shfl_sync(0xffffffffu, base1, l1);
        int pos = grp ? (base1 + __popc(m1 & lt)) : (base0 + __popc(m0 & lt));
        g_perm[pos] = r;
    }
}

// ---------------- kernel 2: sorted-prefix aggregation (scalar, 128 CTAs) ---
// grid (Bc, 8), block 128: each thread owns ONE h column. The tiny node sort
// is recomputed per block (cheap); 4x more CTAs than the float4 version to
// cover the latency-bound serial node loop.
__global__ void k_agg(const float* __restrict__ numbers, const int* __restrict__ is_resp,
                      const int* __restrict__ ids) {
    int b = blockIdx.x;
    int tid = threadIdx.x;
    int h = blockIdx.y * 128 + tid;             // 0..1023
    __shared__ float s_num[Nc], s_w[Nc], s_scale[Nc];
    __shared__ int s_order[Nc], s_c[Nc];
    __shared__ unsigned char s_newgrp[Nc];
    __shared__ int s_cnt;
    if (tid == 0) s_cnt = 0;
    __syncthreads();
    {
        int i = tid;                             // 128 threads == Nc
        s_num[i] = numbers[b*Nc + i];
        s_c[i] = (is_resp[b*Nc + i] == 1) ? 1 : 0;
        int valid = (ids[b*Nc + i] >= 0) ? 1 : 0;
        s_w[i] = valid ? g_alpha[b*Nc + i] : 0.f;
        s_scale[i] = (float)valid;
        if (valid) atomicAdd(&s_cnt, 1);
    }
    __syncthreads();
    float denom = fmaxf((float)(s_cnt - 1), 1.f);
    {
        int i = tid;
        float ni = s_num[i];
        int pos = 0;
        for (int j = 0; j < Nc; j++) {
            float nj = s_num[j];
            pos += (int)((nj < ni) || (nj == ni && j < i));
        }
        s_order[pos] = i;
        s_scale[i] = s_scale[i] / denom;
    }
    __syncthreads();
    {
        int t = tid;
        s_newgrp[t] = (t == 0) || (s_num[s_order[t]] != s_num[s_order[t-1]]);
    }
    __syncthreads();

    const float* initb = g_A + (size_t)(b*Nc)*KTOT + h;
    float A0 = 0.f, A1 = 0.f;
    #pragma unroll 4
    for (int j = 0; j < Nc; j++) {
        float wv = s_w[j] * initb[(size_t)j*KTOT];
        if (s_c[j]) A1 += wv; else A0 += wv;
    }
    float p0 = 0.f, p1 = 0.f, r0 = 0.f, r1 = 0.f;
    float v = initb[(size_t)s_order[0]*KTOT];
    for (int t = 0; t < Nc; t++) {
        int j = s_order[t];
        float vn = 0.f;
        if (t + 1 < Nc) vn = initb[(size_t)s_order[t+1]*KTOT];
        if (s_newgrp[t]) { p0 = r0; p1 = r1; }
        float w = s_w[j], sc = s_scale[j];
        int c = s_c[j];
        float wv = w * v;
        float sub0 = A0 - p0 - (c == 0 ? wv : 0.f);
        float sub1 = A1 - p1 - (c == 1 ? wv : 0.f);
        float* xb = g_A + (size_t)(b*Nc + j)*KTOT + Hc + h;
        xb[0]     = to_tf32(p0 * sc);
        xb[Hc]    = to_tf32(p1 * sc);
        xb[2*Hc]  = to_tf32(sub0 * sc);
        xb[3*Hc]  = to_tf32(sub1 * sc);
        if (c) r1 += wv; else r0 += wv;
        v = vn;
    }
}

// ---------------- kernel 4: tf32 mma.sync GEMM, cp.async 3-stage -----------
// 512 threads, 16 warps (4x4), warp tile 32x32. smem [row][36] padded layout.
__global__ void __launch_bounds__(512, 1)
k_mma(const float* __restrict__ b_f, const float* __restrict__ W_r,
      float* __restrict__ out) {
    extern __shared__ float sdyn[];
    __shared__ int s_rows[MT];
    __shared__ const float* s_Bp[KSEGS];

    int tid = threadIdx.x;
    int wid = tid >> 5;
    int lane = tid & 31;
    int g = lane >> 2, tig = lane & 3;
    int wr = wid >> 2;                // 0..3 (32-row strip)
    int wc = wid & 3;                 // 0..3 (32-col strip)
    int mt = blockIdx.y, nt = blockIdx.x;
    int ncol = nt * NTt;

    if (tid < MT) s_rows[tid] = g_perm[mt*MT + tid];
    if (tid == 0) {
        int a = (mt >= g_meta[0]) ? 1 : 0;
        s_Bp[0] = g_wfT;
        s_Bp[1] = W_r + (size_t)(4 + 2*a)*Hc*Hc;   // raw fp32: HMMA truncates
        s_Bp[2] = W_r + (size_t)(5 + 2*a)*Hc*Hc;
        s_Bp[3] = W_r + (size_t)(2*a    )*Hc*Hc;
        s_Bp[4] = W_r + (size_t)(2*a + 1)*Hc*Hc;
    }
    __syncthreads();

    // copy map: thread t owns 16B units t and t+512 of each 1024-unit tile.
    int mu0 = tid >> 3;               // row 0..63
    int seg = tid & 7;                // 16B segment within 128B row payload
    int mu1 = mu0 + 64;
    int rA0 = s_rows[mu0], rA1 = s_rows[mu1];
    const float* srcA0 = (rA0 >= 0) ? (g_A + (size_t)rA0*KTOT + seg*4) : g_A;
    const float* srcA1 = (rA1 >= 0) ? (g_A + (size_t)rA1*KTOT + seg*4) : g_A;
    int szA0 = (rA0 >= 0) ? 16 : 0;
    int szA1 = (rA1 >= 0) ? 16 : 0;
    int d0 = mu0*KCp*4 + seg*16;      // byte offset within a tile
    int d1 = mu1*KCp*4 + seg*16;
    size_t bc0 = (size_t)(ncol + mu0)*Hc + seg*4;
    size_t bc1 = (size_t)(ncol + mu1)*Hc + seg*4;
    uint32_t sb = (uint32_t)__cvta_generic_to_shared(sdyn);

    auto issue = [&](int kc) {
        int st = kc % NSTG;
        uint32_t ab = sb + st*(STAGE_F*4);
        uint32_t bb = ab + TILE_F*4;
        int koff = kc * KC;
        cpa16(ab + d0, srcA0 + koff, szA0);
        cpa16(ab + d1, srcA1 + koff, szA1);
        const float* Bs = s_Bp[kc >> 5];
        int kin = (kc & 31) * KC;
        cpa16(bb + d0, Bs + bc0 + kin, 16);
        cpa16(bb + d1, Bs + bc1 + kin, 16);
        asm volatile("cp.async.commit_group;" ::: "memory");
    };

    issue(0);
    issue(1);

    float acc[2][4][4];
    #pragma unroll
    for (int i = 0; i < 2; i++)
        #pragma unroll
        for (int j = 0; j < 4; j++)
            #pragma unroll
            for (int q = 0; q < 4; q++) acc[i][j][q] = 0.f;

    for (int kc = 0; kc < NCH; kc++) {
        if (kc + 1 < NCH) asm volatile("cp.async.wait_group 1;" ::: "memory");
        else              asm volatile("cp.async.wait_group 0;" ::: "memory");
        __syncthreads();
        if (kc + 2 < NCH) issue(kc + 2);

        const float* As = sdyn + (kc % NSTG)*STAGE_F;
        const float* Bs = As + TILE_F;
        #pragma unroll
        for (int ks = 0; ks < 4; ks++) {
            int k0 = 8*ks + tig;
            uint32_t afr[2][4], bfr[4][2];
            #pragma unroll
            for (int rm = 0; rm < 2; rm++) {
                int m = 32*wr + 16*rm + g;
                afr[rm][0] = __float_as_uint(As[m*KCp + k0]);
                afr[rm][1] = __float_as_uint(As[(m+8)*KCp + k0]);
                afr[rm][2] = __float_as_uint(As[m*KCp + k0 + 4]);
                afr[rm][3] = __float_as_uint(As[(m+8)*KCp + k0 + 4]);
            }
            #pragma unroll
            for (int nb = 0; nb < 4; nb++) {
                int n = 32*wc + 8*nb + g;
                bfr[nb][0] = __float_as_uint(Bs[n*KCp + k0]);
                bfr[nb][1] = __float_as_uint(Bs[n*KCp + k0 + 4]);
            }
            #pragma unroll
            for (int rm = 0; rm < 2; rm++)
                #pragma unroll
                for (int nb = 0; nb < 4; nb++)
                    mma8(acc[rm][nb], afr[rm], bfr[nb]);
        }
    }

    // ---- epilogue: bias + relu + scatter --------------------------------
    #pragma unroll
    for (int rm = 0; rm < 2; rm++) {
        int m0 = 32*wr + 16*rm + g;
        int row0 = s_rows[m0], row1 = s_rows[m0 + 8];
        #pragma unroll
        for (int nb = 0; nb < 4; nb++) {
            int col = ncol + 32*wc + 8*nb + 2*tig;
            float b0v = b_f[col], b1v = b_f[col + 1];
            if (row0 >= 0) {
                float v0 = acc[rm][nb][0] + b0v; v0 = v0 > 0.f ? v0 : 0.f;
                float v1 = acc[rm][nb][1] + b1v; v1 = v1 > 0.f ? v1 : 0.f;
                *(float2*)(out + (size_t)row0*Hc + col) = make_float2(v0, v1);
            }
            if (row1 >= 0) {
                float v2 = acc[rm][nb][2] + b0v; v2 = v2 > 0.f ? v2 : 0.f;
                float v3 = acc[rm][nb][3] + b1v; v3 = v3 > 0.f ? v3 : 0.f;
                *(float2*)(out + (size_t)row1*Hc + col) = make_float2(v2, v3);
            }
        }
    }
}

// ---------------------------------------------------------------------------
extern "C" void kernel_launch(void* const* d_in, const int* in_sizes, int n_in,
                              void* d_out, int out_size) {
    const float* word_emb = (const float*)d_in[0];
    const int*   num_ids  = (const int*)  d_in[1];
    const int*   is_resp  = (const int*)  d_in[2];
    const float* numbers  = (const float*)d_in[3];
    const float* w_alpha  = (const float*)d_in[4];
    const float* b_alpha  = (const float*)d_in[5];
    const float* w_f      = (const float*)d_in[6];
    const float* b_f      = (const float*)d_in[7];
    const float* W_r      = (const float*)d_in[8];
    float* out = (float*)d_out;

    k_gather<<<ROWS, 256>>>(word_emb, num_ids, w_alpha, b_alpha);
    k_transperm<<<dim3(33, 32), dim3(32, 8)>>>(w_f, is_resp);
    k_agg<<<dim3(Bc, 8), 128>>>(numbers, is_resp, num_ids);

    cudaFuncSetAttribute(k_mma, cudaFuncAttributeMaxDynamicSharedMemorySize, SMEM_BYTES);
    k_mma<<<dim3(NTILES, MTILES), 512, SMEM_BYTES>>>(b_f, W_r, out);
}